// round 9
// baseline (speedup 1.0000x reference)
#include <cuda_runtime.h>

// ---------------------------------------------------------------------------
// STGCN fused kernel for GB300 (sm_103a)
// x: [64, 512, 2, 21, 2]  ->  out: [64, 512, 2, 64]  (fp32)
// One fused kernel; CTA = (b, hand, T-tile of 32); 672 threads = (v, c).
// All intermediates in SMEM. BN folded into conv weights by a prep kernel.
// Channel reductions use packed fma.rn.f32x2 (FFMA2): operands come directly
// from 16B vector SMEM loads, so packing costs zero extra instructions.
// ---------------------------------------------------------------------------

#define NPARAMS 7904

// packed folded parameter block (float offsets)
#define OFF_A    0      // 441  : normalized adjacency [v][u]   (pad to 448)
#define OFF_W0T  448    // 64   : gcn0 weights [ci][c]
#define OFF_GB0  512    // 32   : gcn0 bias
#define OFF_WT0  544    // 3072 : tcn0 weights folded w/ bn0, [k][i4][c][4]
#define OFF_B0   3616   // 32   : folded tcn0+bn0 bias
#define OFF_RW   3648   // 64   : residual conv weights folded w/ res_bn [ci][c]
#define OFF_RB   3712   // 32   : folded residual bias
#define OFF_W1T  3744   // 1024 : gcn1 weights [i4][c][4]
#define OFF_GB1  4768   // 32   : gcn1 bias
#define OFF_WT1  4800   // 3072 : tcn1 weights folded w/ bn1, [k][i4][c][4]
#define OFF_B1   7872   // 32   : folded tcn1+bn1 bias

// shared memory layout (float offsets)
#define SM_XS    7904          // 36*42  = 1512   (input tile with halo 2)
#define SM_BUF2  9416          // 34*672 = 22848  (y1 scratch / h1 / h2)
#define SM_BUF1  32264         // 36*672 = 24192  (y2 / z1 / z2 / fc stage)
#define SM_TOTALF 56456        // 225824 bytes

__device__ float d_params[NPARAMS];
__device__ float d_fcwT[64 * 672];   // fc weights: [o][p], p = v*32+c

typedef unsigned long long u64;

static __device__ __forceinline__ float4 ld4(const float* p) {
    return *reinterpret_cast<const float4*>(p);
}
static __device__ __forceinline__ void st4(float* p, float4 v) {
    *reinterpret_cast<float4*>(p) = v;
}
// 16B load viewed as two packed f32x2 operands (x = floats 0,1; y = floats 2,3)
static __device__ __forceinline__ ulonglong2 ld2x2(const float* p) {
    return *reinterpret_cast<const ulonglong2*>(p);
}
// packed FFMA2: elementwise (a.lo*b.lo+c.lo, a.hi*b.hi+c.hi)
static __device__ __forceinline__ u64 ffma2(u64 a, u64 b, u64 c) {
    u64 d;
    asm("fma.rn.f32x2 %0, %1, %2, %3;" : "=l"(d) : "l"(a), "l"(b), "l"(c));
    return d;
}
// horizontal sum of one packed f32x2
static __device__ __forceinline__ float hsum2(u64 p) {
    float lo, hi;
    asm("mov.b64 {%0, %1}, %2;" : "=f"(lo), "=f"(hi) : "l"(p));
    return lo + hi;
}

// ---------------------------------------------------------------------------
// temporal conv accumulate (packed): U outputs per thread, 3-tap window
// bi layout: [slot][v*32 + i], w layout: [k][i4][c][4] (bn-folded)
// input loads are warp-broadcast (address independent of lane c)
// ---------------------------------------------------------------------------
template<int U>
__device__ __forceinline__ void conv_acc2(const float* __restrict__ bi,
                                          const float* __restrict__ w,
                                          int base, int voff, int c,
                                          float* acc)
{
    u64 alo[U], ahi[U];
#pragma unroll
    for (int u = 0; u < U; u++) { alo[u] = 0ull; ahi[u] = 0ull; }
#pragma unroll
    for (int i4 = 0; i4 < 8; i4++) {
        ulonglong2 in[U + 2];
#pragma unroll
        for (int j = 0; j < U + 2; j++)
            in[j] = ld2x2(bi + (base + j) * 672 + voff + i4 * 4);
#pragma unroll
        for (int k = 0; k < 3; k++) {
            ulonglong2 wk = ld2x2(w + ((k * 8 + i4) * 32 + c) * 4);
#pragma unroll
            for (int u = 0; u < U; u++) {
                alo[u] = ffma2(wk.x, in[u + k].x, alo[u]);
                ahi[u] = ffma2(wk.y, in[u + k].y, ahi[u]);
            }
        }
    }
#pragma unroll
    for (int u = 0; u < U; u++) acc[u] = hsum2(alo[u]) + hsum2(ahi[u]);
}

// Phase B: tconv0 + folded bn0 + conv-residual + relu -> h1 (34 slots, buf2)
template<int U>
__device__ __forceinline__ void phaseB(const float* __restrict__ buf1,
                                       float* __restrict__ buf2,
                                       const float* __restrict__ wt0,
                                       const float* __restrict__ xs,
                                       int s0, int voff, int v, int c,
                                       float bias0c, float rw0, float rw1, float rbc)
{
    float acc[U];
    conv_acc2<U>(buf1, wt0, s0, voff, c, acc);
#pragma unroll
    for (int u = 0; u < U; u++) {
        int sp = s0 + u;                   // h1 slot, t = t0-1+sp
        float res = fmaf(rw0, xs[(sp + 1) * 42 + v * 2],
                    fmaf(rw1, xs[(sp + 1) * 42 + v * 2 + 1], rbc));
        buf2[sp * 672 + voff + c] = fmaxf(acc[u] + bias0c + res, 0.0f);
    }
}

// Phase C1: graph gather block1: z1[s][v][i] = sum_u A[v][u]*h1[s][u][i]
// (LDS-crossbar-bound; scalar. Quarter-warp phases are 128B-contiguous ->
//  conflict-free despite cross-quarter bank aliasing.)
template<int U>
__device__ __forceinline__ void c1_group(const float* __restrict__ h1,
                                         float* __restrict__ z1,
                                         const float* __restrict__ Ah,
                                         int sb, int vv, int ii4)
{
    float4 acc[U];
#pragma unroll
    for (int j = 0; j < U; j++) { acc[j].x = 0.f; acc[j].y = 0.f; acc[j].z = 0.f; acc[j].w = 0.f; }
    for (int u = 0; u < 21; u++) {
        float a = Ah[vv * 21 + u];
#pragma unroll
        for (int j = 0; j < U; j++) {
            float4 in = ld4(h1 + (sb + j) * 672 + u * 32 + ii4 * 4);
            acc[j].x = fmaf(a, in.x, acc[j].x);
            acc[j].y = fmaf(a, in.y, acc[j].y);
            acc[j].z = fmaf(a, in.z, acc[j].z);
            acc[j].w = fmaf(a, in.w, acc[j].w);
        }
    }
#pragma unroll
    for (int j = 0; j < U; j++)
        st4(z1 + (sb + j) * 672 + vv * 32 + ii4 * 4, acc[j]);
}

// Phase C2: z2[s][v][c] = gb1[c] + sum_i w1t[i][c]*z1[s][v][i], in-place
// (warp-private row v; packed FFMA2)
template<int U>
__device__ __forceinline__ void c2_group(float* __restrict__ buf1,
                                         const float* __restrict__ w1t,
                                         int sb, int voff, int c, float gb, int tbase)
{
    u64 alo[U], ahi[U];
#pragma unroll
    for (int u = 0; u < U; u++) { alo[u] = 0ull; ahi[u] = 0ull; }
#pragma unroll
    for (int i4 = 0; i4 < 8; i4++) {
        ulonglong2 wk = ld2x2(w1t + (i4 * 32 + c) * 4);
#pragma unroll
        for (int u = 0; u < U; u++) {
            ulonglong2 in = ld2x2(buf1 + (sb + u) * 672 + voff + i4 * 4);
            alo[u] = ffma2(wk.x, in.x, alo[u]);
            ahi[u] = ffma2(wk.y, in.y, ahi[u]);
        }
    }
    __syncwarp();   // whole warp (owner of row v) finished reading before overwrite
#pragma unroll
    for (int u = 0; u < U; u++) {
        int t = tbase + u;
        float val = gb + hsum2(alo[u]) + hsum2(ahi[u]);
        buf1[(sb + u) * 672 + voff + c] = ((unsigned)t < 512u) ? val : 0.0f;  // T zero-pad
    }
}

// Phase D: tconv1 + folded bn1 + identity residual + relu -> h2 (buf2, in place)
template<int U>
__device__ __forceinline__ void phaseD(const float* __restrict__ buf1,
                                       float* __restrict__ buf2,
                                       const float* __restrict__ wt1,
                                       int u0, int voff, int c, float bias1c)
{
    float acc[U];
    conv_acc2<U>(buf1, wt1, u0, voff, c, acc);
#pragma unroll
    for (int u = 0; u < U; u++) {
        int slot = u0 + u + 1;             // h1/h2 slot for t = t0+u0+u
        float h = acc[u] + bias1c + buf2[slot * 672 + voff + c];   // thread-private element
        buf2[slot * 672 + voff + c] = fmaxf(h, 0.0f);
    }
}

// ---------------------------------------------------------------------------
// prep kernel: build normalized adjacency, fold BNs into weights, transpose,
// permute fc weights into __device__ globals. Deterministic, runs every launch.
// ---------------------------------------------------------------------------
__global__ void stgcn_prep(const float* __restrict__ gcn_w0, const float* __restrict__ gcn_b0,
                           const float* __restrict__ tcn_w0, const float* __restrict__ tcn_b0,
                           const float* __restrict__ bn_g0, const float* __restrict__ bn_b0,
                           const float* __restrict__ bn_m0, const float* __restrict__ bn_v0,
                           const float* __restrict__ res_w, const float* __restrict__ res_b,
                           const float* __restrict__ res_bn_g, const float* __restrict__ res_bn_b,
                           const float* __restrict__ res_bn_m, const float* __restrict__ res_bn_v,
                           const float* __restrict__ gcn_w1, const float* __restrict__ gcn_b1,
                           const float* __restrict__ tcn_w1, const float* __restrict__ tcn_b1,
                           const float* __restrict__ bn_g1, const float* __restrict__ bn_b1,
                           const float* __restrict__ bn_m1, const float* __restrict__ bn_v1,
                           const float* __restrict__ fc_w)
{
    __shared__ float As[441];
    __shared__ float dg[21];
    int tid = threadIdx.x;
    int gid = blockIdx.x * blockDim.x + tid;
    int gsz = gridDim.x * blockDim.x;

    if (blockIdx.x == 0) {
        for (int i = tid; i < 441; i += blockDim.x) As[i] = 0.0f;
        __syncthreads();
        if (tid == 0) {
            const int ca[20] = {0,1,2,3,0,5,6,7,0,9,10,11,0,13,14,15,0,17,18,19};
            const int cb[20] = {1,2,3,4,5,6,7,8,9,10,11,12,13,14,15,16,17,18,19,20};
            for (int e = 0; e < 20; e++) { As[ca[e]*21+cb[e]] = 1.0f; As[cb[e]*21+ca[e]] = 1.0f; }
            for (int i = 0; i < 21; i++) As[i*21+i] = 1.0f;
        }
        __syncthreads();
        if (tid < 21) {
            float s = 0.0f;
            for (int j = 0; j < 21; j++) s += As[tid*21+j];
            dg[tid] = rsqrtf(s);
        }
        __syncthreads();
        for (int i = tid; i < 441; i += blockDim.x) {
            int r = i / 21, cc = i - r * 21;
            d_params[OFF_A + i] = As[i] * dg[r] * dg[cc];
        }
    }

    for (int i = gid; i < 64; i += gsz) {           // gcn0 W^T [ci][c]
        int ci = i >> 5, c = i & 31;
        d_params[OFF_W0T + i] = gcn_w0[c * 2 + ci];
    }
    for (int i = gid; i < 32; i += gsz) d_params[OFF_GB0 + i] = gcn_b0[i];
    for (int i = gid; i < 3072; i += gsz) {         // tcn0 folded: [k][i4][c][4]
        int cc = i & 3, c = (i >> 2) & 31, i4 = (i >> 7) & 7, k = i >> 10;
        int ii = i4 * 4 + cc;
        float s0 = bn_g0[c] * rsqrtf(bn_v0[c] + 1e-5f);
        d_params[OFF_WT0 + i] = tcn_w0[(c * 32 + ii) * 3 + k] * s0;
    }
    for (int i = gid; i < 32; i += gsz) {
        float s0 = bn_g0[i] * rsqrtf(bn_v0[i] + 1e-5f);
        d_params[OFF_B0 + i] = (tcn_b0[i] - bn_m0[i]) * s0 + bn_b0[i];
    }
    for (int i = gid; i < 64; i += gsz) {           // residual conv folded
        int ci = i >> 5, c = i & 31;
        float rs = res_bn_g[c] * rsqrtf(res_bn_v[c] + 1e-5f);
        d_params[OFF_RW + i] = res_w[c * 2 + ci] * rs;
    }
    for (int i = gid; i < 32; i += gsz) {
        float rs = res_bn_g[i] * rsqrtf(res_bn_v[i] + 1e-5f);
        d_params[OFF_RB + i] = (res_b[i] - res_bn_m[i]) * rs + res_bn_b[i];
    }
    for (int i = gid; i < 1024; i += gsz) {         // gcn1 W^T [i4][c][4]
        int cc = i & 3, c = (i >> 2) & 31, i4 = i >> 7;
        int ii = i4 * 4 + cc;
        d_params[OFF_W1T + i] = gcn_w1[c * 32 + ii];
    }
    for (int i = gid; i < 32; i += gsz) d_params[OFF_GB1 + i] = gcn_b1[i];
    for (int i = gid; i < 3072; i += gsz) {         // tcn1 folded
        int cc = i & 3, c = (i >> 2) & 31, i4 = (i >> 7) & 7, k = i >> 10;
        int ii = i4 * 4 + cc;
        float s1 = bn_g1[c] * rsqrtf(bn_v1[c] + 1e-5f);
        d_params[OFF_WT1 + i] = tcn_w1[(c * 32 + ii) * 3 + k] * s1;
    }
    for (int i = gid; i < 32; i += gsz) {
        float s1 = bn_g1[i] * rsqrtf(bn_v1[i] + 1e-5f);
        d_params[OFF_B1 + i] = (tcn_b1[i] - bn_m1[i]) * s1 + bn_b1[i];
    }
    for (int i = gid; i < 64 * 672; i += gsz) {     // fc transposed: [o][p], p=v*32+c, ref j=c*21+v
        int o = i / 672, p = i - o * 672;
        int v = p >> 5, c = p & 31;
        d_fcwT[i] = fc_w[o * 672 + c * 21 + v];
    }
}

// ---------------------------------------------------------------------------
// main fused kernel
// ---------------------------------------------------------------------------
__global__ void __launch_bounds__(672, 1)
stgcn_main(const float* __restrict__ x, const float* __restrict__ fcb,
           float* __restrict__ out)
{
    extern __shared__ float sm[];
    const int tid = threadIdx.x;
    const int bx = blockIdx.x;
    const int tile = bx & 15, hand = (bx >> 4) & 1, b = bx >> 5;
    const int t0 = tile * 32;
    const int v = tid >> 5, c = tid & 31, voff = v * 32;

    float* xs   = sm + SM_XS;
    float* buf2 = sm + SM_BUF2;
    float* buf1 = sm + SM_BUF1;
    const float* Ah = sm + OFF_A;

    // ---- load packed params + input tile (halo 2), zero-pad T bounds
    for (int i = tid; i < NPARAMS; i += 672) sm[i] = d_params[i];
    for (int i = tid; i < 36 * 42; i += 672) {
        int s = i / 42, r = i - s * 42;
        int t = t0 - 2 + s;
        float val = 0.0f;
        if ((unsigned)t < 512u)
            val = x[((b * 512 + t) * 2 + hand) * 42 + r];
        xs[i] = val;
    }
    __syncthreads();

    // ---- A1: y1[s][v][ci] = sum_u A[v][u] * x[s][u][ci]   (into buf2 scratch)
    for (int i = tid; i < 36 * 42; i += 672) {
        int s = i / 42, r = i - s * 42, vv = r >> 1, ci = r & 1;
        const float* arow = Ah + vv * 21;
        const float* xrow = xs + s * 42 + ci;
        float acc = 0.0f;
#pragma unroll
        for (int u = 0; u < 21; u++) acc = fmaf(arow[u], xrow[u * 2], acc);
        buf2[i] = acc;
    }
    __syncthreads();

    // ---- A2: y2 = gcn0 projection (2 -> 32) into buf1; zero for out-of-range t
    {
        float w00 = sm[OFF_W0T + c], w01 = sm[OFF_W0T + 32 + c], g0 = sm[OFF_GB0 + c];
        for (int s = 0; s < 36; s++) {
            int t = t0 - 2 + s;
            float val = 0.0f;
            if ((unsigned)t < 512u)
                val = fmaf(w00, buf2[s * 42 + v * 2], fmaf(w01, buf2[s * 42 + v * 2 + 1], g0));
            buf1[s * 672 + voff + c] = val;
        }
    }
    __syncthreads();

    // ---- B: h1 = relu(tconv0_bn(y2) + res0)   (34 slots into buf2)
    {
        const float* wt0 = sm + OFF_WT0;
        float bias0c = sm[OFF_B0 + c];
        float rw0 = sm[OFF_RW + c], rw1 = sm[OFF_RW + 32 + c], rbc = sm[OFF_RB + c];
        phaseB<6>(buf1, buf2, wt0, xs, 0,  voff, v, c, bias0c, rw0, rw1, rbc);
        phaseB<6>(buf1, buf2, wt0, xs, 6,  voff, v, c, bias0c, rw0, rw1, rbc);
        phaseB<6>(buf1, buf2, wt0, xs, 12, voff, v, c, bias0c, rw0, rw1, rbc);
        phaseB<6>(buf1, buf2, wt0, xs, 18, voff, v, c, bias0c, rw0, rw1, rbc);
        phaseB<6>(buf1, buf2, wt0, xs, 24, voff, v, c, bias0c, rw0, rw1, rbc);
        phaseB<4>(buf1, buf2, wt0, xs, 30, voff, v, c, bias0c, rw0, rw1, rbc);
    }
    __syncthreads();

    // ---- C1: z1 = A-gather of h1 (34 slots into buf1)
    {
        // lane mapping: low 3 bits = i4 (contiguous 128B per quarter-warp), bits 3..4 = q
        int vv  = tid >> 5;
        int ii4 = tid & 7;
        int q   = (tid >> 3) & 3;
        if (q < 3) c1_group<9>(buf2, buf1, Ah, 9 * q, vv, ii4);
        else       c1_group<7>(buf2, buf1, Ah, 27,    vv, ii4);
    }
    __syncthreads();

    // ---- C2: z2 = gcn1 projection, in place in buf1 (zero out-of-range t)
    {
        const float* w1t = sm + OFF_W1T;
        float gb1c = sm[OFF_GB1 + c];
        c2_group<6>(buf1, w1t, 0,  voff, c, gb1c, t0 - 1);
        c2_group<6>(buf1, w1t, 6,  voff, c, gb1c, t0 + 5);
        c2_group<6>(buf1, w1t, 12, voff, c, gb1c, t0 + 11);
        c2_group<6>(buf1, w1t, 18, voff, c, gb1c, t0 + 17);
        c2_group<6>(buf1, w1t, 24, voff, c, gb1c, t0 + 23);
        c2_group<4>(buf1, w1t, 30, voff, c, gb1c, t0 + 29);
    }
    __syncthreads();

    // ---- D: h2 = relu(tconv1_bn(z2) + h1)   (buf2 slots 1..32, in place)
    {
        const float* wt1 = sm + OFF_WT1;
        float bias1c = sm[OFF_B1 + c];
        phaseD<6>(buf1, buf2, wt1, 0,  voff, c, bias1c);
        phaseD<6>(buf1, buf2, wt1, 6,  voff, c, bias1c);
        phaseD<6>(buf1, buf2, wt1, 12, voff, c, bias1c);
        phaseD<6>(buf1, buf2, wt1, 18, voff, c, bias1c);
        phaseD<6>(buf1, buf2, wt1, 24, voff, c, bias1c);
        phaseD<2>(buf1, buf2, wt1, 30, voff, c, bias1c);
    }

    // ---- FC: out[t][o] = fc_b[o] + sum_p h2[t][p] * fcwT[o][p]
    // threads 0..511: o = tid&63, tq = tid>>6 (4 t's per thread, h loads warp-broadcast)
    // weights staged transposed in buf1 with row stride 340 (conflict-free 16B loads)
    u64 a0l = 0ull, a0h = 0ull, a1l = 0ull, a1h = 0ull;
    u64 a2l = 0ull, a2h = 0ull, a3l = 0ull, a3h = 0ull;
    const int o = tid & 63, tq = tid >> 6;
    for (int ch = 0; ch < 2; ch++) {
        const int p0 = ch * 336;
        __syncthreads();   // previous buf1 readers (D / prior chunk) done; D's buf2 writes visible
        for (int i = tid; i < 64 * 336; i += 672) {
            int oo = i / 336, pi = i - oo * 336;
            buf1[oo * 340 + pi] = d_fcwT[oo * 672 + p0 + pi];
        }
        __syncthreads();
        if (tid < 512) {
            const float* wrow = buf1 + o * 340;
            const float* hb0  = buf2 + (tq * 4 + 1) * 672 + p0;
#pragma unroll 4
            for (int pi4 = 0; pi4 < 84; pi4++) {
                ulonglong2 w  = ld2x2(wrow + pi4 * 4);
                ulonglong2 h0 = ld2x2(hb0 + pi4 * 4);
                ulonglong2 h1 = ld2x2(hb0 + 672  + pi4 * 4);
                ulonglong2 h2 = ld2x2(hb0 + 1344 + pi4 * 4);
                ulonglong2 h3 = ld2x2(hb0 + 2016 + pi4 * 4);
                a0l = ffma2(w.x, h0.x, a0l);  a0h = ffma2(w.y, h0.y, a0h);
                a1l = ffma2(w.x, h1.x, a1l);  a1h = ffma2(w.y, h1.y, a1h);
                a2l = ffma2(w.x, h2.x, a2l);  a2h = ffma2(w.y, h2.y, a2h);
                a3l = ffma2(w.x, h3.x, a3l);  a3h = ffma2(w.y, h3.y, a3h);
            }
        }
    }
    if (tid < 512) {
        float bo = fcb[o];
        int tb = t0 + tq * 4;
        out[((b * 512 + tb + 0) * 2 + hand) * 64 + o] = hsum2(a0l) + hsum2(a0h) + bo;
        out[((b * 512 + tb + 1) * 2 + hand) * 64 + o] = hsum2(a1l) + hsum2(a1h) + bo;
        out[((b * 512 + tb + 2) * 2 + hand) * 64 + o] = hsum2(a2l) + hsum2(a2h) + bo;
        out[((b * 512 + tb + 3) * 2 + hand) * 64 + o] = hsum2(a3l) + hsum2(a3h) + bo;
    }
}

// ---------------------------------------------------------------------------
extern "C" void kernel_launch(void* const* d_in, const int* in_sizes, int n_in,
                              void* d_out, int out_size)
{
    const float* x        = (const float*)d_in[0];
    const float* gcn_w0   = (const float*)d_in[1];
    const float* gcn_b0   = (const float*)d_in[2];
    const float* tcn_w0   = (const float*)d_in[3];
    const float* tcn_b0   = (const float*)d_in[4];
    const float* bn_g0    = (const float*)d_in[5];
    const float* bn_b0    = (const float*)d_in[6];
    const float* bn_m0    = (const float*)d_in[7];
    const float* bn_v0    = (const float*)d_in[8];
    const float* res_w    = (const float*)d_in[9];
    const float* res_b    = (const float*)d_in[10];
    const float* res_bn_g = (const float*)d_in[11];
    const float* res_bn_b = (const float*)d_in[12];
    const float* res_bn_m = (const float*)d_in[13];
    const float* res_bn_v = (const float*)d_in[14];
    const float* gcn_w1   = (const float*)d_in[15];
    const float* gcn_b1   = (const float*)d_in[16];
    const float* tcn_w1   = (const float*)d_in[17];
    const float* tcn_b1   = (const float*)d_in[18];
    const float* bn_g1    = (const float*)d_in[19];
    const float* bn_b1    = (const float*)d_in[20];
    const float* bn_m1    = (const float*)d_in[21];
    const float* bn_v1    = (const float*)d_in[22];
    const float* fc_w     = (const float*)d_in[23];
    const float* fc_b     = (const float*)d_in[24];
    float* out = (float*)d_out;

    const size_t smem_bytes = (size_t)SM_TOTALF * sizeof(float);
    cudaFuncSetAttribute(stgcn_main, cudaFuncAttributeMaxDynamicSharedMemorySize,
                         (int)smem_bytes);

    stgcn_prep<<<96, 256>>>(gcn_w0, gcn_b0, tcn_w0, tcn_b0, bn_g0, bn_b0, bn_m0, bn_v0,
                            res_w, res_b, res_bn_g, res_bn_b, res_bn_m, res_bn_v,
                            gcn_w1, gcn_b1, tcn_w1, tcn_b1, bn_g1, bn_b1, bn_m1, bn_v1,
                            fc_w);
    stgcn_main<<<2048, 672, smem_bytes>>>(x, fc_b, out);
}